// round 8
// baseline (speedup 1.0000x reference)
#include <cuda_runtime.h>

#define BS    64
#define NC    80
#define NA    8400
#define TOPK  13
#define EPSF  1e-9f

#define ATHR  1024
#define HALF  (NA / 2)          // 4200 anchors per half-row block
#define ELEM  5                 // ceil(4200 / 1024)
#define NWARP (ATHR / 32)
#define GRID  (BS * 2)          // 128 blocks, single wave (<=148 SMs)

#define PB_ANCH 66              // phase-B anchors per block: 128*66 = 8448 >= 8400

// norm_align_metric scratch (float bits). Zeroed at load; phase B resets its
// own slice after reading, so it's zeroed again before every next call.
__device__ unsigned int d_norm_bits[NA];
// Per-half-row sorted top-13 candidate lists (u64 packed), padded to 16.
__device__ unsigned long long d_halftop[GRID * 16];
// Monotone ticket counters for the two single-wave grid syncs (never reset).
__device__ unsigned int d_arrive1;
__device__ unsigned int d_arrive2;

static __device__ __forceinline__ unsigned long long u64max(unsigned long long a,
                                                            unsigned long long b) {
    return a > b ? a : b;
}

static __device__ __forceinline__ void grid_sync(unsigned int* ctr, int tid) {
    __syncthreads();
    if (tid == 0) {
        __threadfence();
        unsigned old = atomicAdd(ctr, 1u);
        unsigned tgt = (old & ~(unsigned)(GRID - 1)) + GRID;
        while (*(volatile unsigned*)ctr < tgt) { }
        __threadfence();
    }
    __syncthreads();
}

// 128 blocks: block bid handles half h = bid&1 of row b = bid>>1.
__global__ __launch_bounds__(ATHR, 1) void taa_fused(
    const float* __restrict__ pd_scores,   // (BS, NC, NA)
    const float* __restrict__ pd_bboxes,   // (BS, 4, NA)
    const int*   __restrict__ gt_labels,   // (BS,)
    const float* __restrict__ gt_bboxes,   // (BS, 4)
    float*       __restrict__ target_out,  // (NA, BS)
    float*       __restrict__ mask_out)    // (BS, NA)
{
    __shared__ unsigned long long s_cand[TOPK * NWARP];
    __shared__ unsigned long long s_top[TOPK];
    __shared__ float s_topv[TOPK];
    __shared__ int   s_topi[TOPK];
    __shared__ float s_iou[TOPK];
    __shared__ float s_ratio;
    __shared__ float s_lab[BS];

    const int bid  = blockIdx.x;
    const int b    = bid >> 1;          // batch row
    const int h    = bid & 1;           // half index
    const int tid  = threadIdx.x;
    const int lane = tid & 31;
    const int wid  = tid >> 5;

    if (tid < BS) s_lab[tid] = (float)gt_labels[tid];

    const float gx1 = gt_bboxes[b * 4 + 0];
    const float gy1 = gt_bboxes[b * 4 + 1];
    const float gx2 = gt_bboxes[b * 4 + 2];
    const float gy2 = gt_bboxes[b * 4 + 3];
    const float area1 = fmaxf(gx2 - gx1, 0.f) * fmaxf(gy2 - gy1, 0.f);
    const int   label = gt_labels[b];

    const float* __restrict__ px1 = pd_bboxes + ((long)b * 4 + 0) * NA;
    const float* __restrict__ py1 = pd_bboxes + ((long)b * 4 + 1) * NA;
    const float* __restrict__ px2 = pd_bboxes + ((long)b * 4 + 2) * NA;
    const float* __restrict__ py2 = pd_bboxes + ((long)b * 4 + 3) * NA;
    const float* __restrict__ sc  = pd_scores + ((long)b * NC + label) * NA;
    float* __restrict__ mrow = mask_out + (long)b * NA;

    // ---- Phase A.1: align metric over this half-row -> packed u64 candidates.
    // pack = (float_bits(align) << 32) | (0xFFFFFFFF - global_anchor):
    // u64 max == (higher align, then lower anchor) == jax top_k tie order.
    const int abase = h * HALF;
    unsigned long long p[ELEM];
    #pragma unroll
    for (int i = 0; i < ELEM; i++) {
        int al = i * ATHR + tid;
        if (al < HALF) {
            int a = abase + al;
            float bx1 = px1[a], by1 = py1[a], bx2 = px2[a], by2 = py2[a];
            float iw = fmaxf(fminf(gx2, bx2) - fmaxf(gx1, bx1), 0.f);
            float ih = fmaxf(fminf(gy2, by2) - fmaxf(gy1, by1), 0.f);
            float ov = iw * ih;
            float a2 = fmaxf(bx2 - bx1, 0.f) * fmaxf(by2 - by1, 0.f);
            float iou = ov / (area1 + a2 - ov + EPSF);
            float iou2 = iou * iou;
            float align = sc[a] * (iou2 * iou2 * iou2);
            p[i] = ((unsigned long long)__float_as_uint(align) << 32)
                 | (unsigned long long)(0xFFFFFFFFu - (unsigned)a);
            mrow[a] = 0.0f;
        } else {
            p[i] = 0ull;
        }
    }

    // ---- Stage 1: per-warp top-13 (butterfly shuffles, no barriers).
    #pragma unroll
    for (int k = 0; k < TOPK; k++) {
        unsigned long long m = 0ull;
        #pragma unroll
        for (int i = 0; i < ELEM; i++) m = u64max(m, p[i]);
        #pragma unroll
        for (int o = 16; o > 0; o >>= 1)
            m = u64max(m, __shfl_xor_sync(0xFFFFFFFFu, m, o));
        if (lane == 0) s_cand[k * NWARP + wid] = m;
        #pragma unroll
        for (int i = 0; i < ELEM; i++) if (p[i] == m) p[i] = 0ull;
    }
    __syncthreads();

    // ---- Stage 2: warp 0 merges 32*13 candidates -> sorted half top-13
    //      -> global scratch list.
    if (wid == 0) {
        unsigned long long q[TOPK];
        #pragma unroll
        for (int j = 0; j < TOPK; j++) q[j] = s_cand[j * NWARP + lane];
        #pragma unroll
        for (int k = 0; k < TOPK; k++) {
            unsigned long long m = 0ull;
            #pragma unroll
            for (int j = 0; j < TOPK; j++) m = u64max(m, q[j]);
            #pragma unroll
            for (int o = 16; o > 0; o >>= 1)
                m = u64max(m, __shfl_xor_sync(0xFFFFFFFFu, m, o));
            if (lane == 0) d_halftop[bid * 16 + k] = m;
            #pragma unroll
            for (int j = 0; j < TOPK; j++) if (q[j] == m) q[j] = 0ull;
        }
    }

    // ---- Grid sync #1: all half-lists visible.
    grid_sync(&d_arrive1, tid);

    // ---- Finalize (even blocks only; one per row): merge two sorted 13-lists,
    //      exact row top-13, iou recompute, mask + norm scatter.
    if (h == 0) {
        if (wid == 0) {
            unsigned long long c = 0ull;
            if (lane < TOPK)            c = d_halftop[(2 * b) * 16 + lane];
            else if (lane < 2 * TOPK)   c = d_halftop[(2 * b + 1) * 16 + (lane - TOPK)];
            #pragma unroll
            for (int k = 0; k < TOPK; k++) {
                unsigned long long m = c;
                #pragma unroll
                for (int o = 16; o > 0; o >>= 1)
                    m = u64max(m, __shfl_xor_sync(0xFFFFFFFFu, m, o));
                if (lane == 0) s_top[k] = m;
                if (c == m) c = 0ull;
            }
        }
        __syncthreads();

        if (tid < TOPK) {
            unsigned long long w = s_top[tid];
            float v = __uint_as_float((unsigned)(w >> 32));
            int   a = (int)(0xFFFFFFFFu - (unsigned)(w & 0xFFFFFFFFull));
            s_topv[tid] = v;
            s_topi[tid] = a;
            float bx1 = px1[a], by1 = py1[a], bx2 = px2[a], by2 = py2[a];
            float iw = fmaxf(fminf(gx2, bx2) - fmaxf(gx1, bx1), 0.f);
            float ih = fmaxf(fminf(gy2, by2) - fmaxf(gy1, by1), 0.f);
            float ov = iw * ih;
            float a2 = fmaxf(bx2 - bx1, 0.f) * fmaxf(by2 - by1, 0.f);
            s_iou[tid] = ov / (area1 + a2 - ov + EPSF);
        }
        __syncthreads();

        if (tid == 0) {
            float po = 0.f;
            #pragma unroll
            for (int k = 0; k < TOPK; k++) po = fmaxf(po, s_iou[k]);
            s_ratio = po / (s_topv[0] + EPSF);
        }
        __syncthreads();

        if (s_topv[0] > EPSF && tid < TOPK) {
            int a = s_topi[tid];
            mrow[a] = 1.0f;
            float contrib = s_topv[tid] * s_ratio;
            atomicMax(&d_norm_bits[a], __float_as_uint(contrib));
        }
        // invalid row: mask all-zero (cnt>1 collapse), no norm contribution.
    }

    // ---- Grid sync #2: all norm contributions visible.
    grid_sync(&d_arrive2, tid);

    // ---- Phase B: target_scores[a, j] = lab[j] * norm[a], (NA, BS) layout.
    const int a0 = bid * PB_ANCH;
    const int nA = (a0 + PB_ANCH <= NA) ? PB_ANCH : (NA - a0);
    const int la = tid >> 4;            // 0..63 anchors per sweep
    const int j4 = (tid & 15) << 2;     // column group of 4

    #pragma unroll
    for (int it = 0; it < 2; it++) {    // 2*64 = 128 >= 66
        int al = it * 64 + la;
        if (al < nA) {
            int a = a0 + al;
            float nv = __uint_as_float(d_norm_bits[a]);
            float4 v = make_float4(nv * s_lab[j4 + 0], nv * s_lab[j4 + 1],
                                   nv * s_lab[j4 + 2], nv * s_lab[j4 + 3]);
            *reinterpret_cast<float4*>(target_out + (long)a * BS + j4) = v;
        }
    }
    __syncthreads();
    if (tid < nA) d_norm_bits[a0 + tid] = 0u;   // reset own slice for next call
}

extern "C" void kernel_launch(void* const* d_in, const int* in_sizes, int n_in,
                              void* d_out, int out_size) {
    const float* pd_scores = (const float*)d_in[0];
    const float* pd_bboxes = (const float*)d_in[1];
    const int*   gt_labels = (const int*)d_in[2];
    const float* gt_bboxes = (const float*)d_in[3];

    float* target = (float*)d_out;                       // (NA, BS)
    float* mask   = (float*)d_out + (size_t)NA * BS;     // (BS, NA)

    taa_fused<<<GRID, ATHR>>>(pd_scores, pd_bboxes, gt_labels, gt_bboxes,
                              target, mask);
}

// round 9
// speedup vs baseline: 1.2133x; 1.2133x over previous
#include <cuda_runtime.h>

#define BS    64
#define NC    80
#define NA    8400
#define TOPK  13
#define EPSF  1e-9f

#define ATHR  1024
#define ELEM  9            // ceil(NA / ATHR)
#define NWARP (ATHR / 32)

#define PB_ANCH 132        // phase-B anchors per block: 64*132 = 8448 >= 8400

// norm_align_metric scratch (float bits). Zeroed at load; phase B resets its
// own slice after reading, so it's zeroed again before every next call.
__device__ unsigned int d_norm_bits[NA];
// Monotone ticket counter for the single-wave grid sync (never reset).
__device__ unsigned int d_arrive;

// Fused kernel: 64 blocks (one per batch row), 1024 threads, single wave.
// Candidate encoding: sval = float_bits(align) + 1  (u32; align >= 0 so the
// map is strictly monotone; 0 = consumed / out-of-range sentinel, and real
// align 0.0 maps to 1, staying selectable exactly like jax top_k).
// Winner per round = (max sval, then min anchor) == top_k tie order.
__global__ __launch_bounds__(ATHR, 1) void taa_fused(
    const float* __restrict__ pd_scores,   // (BS, NC, NA)
    const float* __restrict__ pd_bboxes,   // (BS, 4, NA)
    const int*   __restrict__ gt_labels,   // (BS,)
    const float* __restrict__ gt_bboxes,   // (BS, 4)
    float*       __restrict__ target_out,  // (NA, BS)
    float*       __restrict__ mask_out)    // (BS, NA)
{
    __shared__ unsigned s_candv[TOPK * NWARP];   // [k*NWARP + warp]
    __shared__ unsigned s_candi[TOPK * NWARP];
    __shared__ float s_topv[TOPK];
    __shared__ int   s_topi[TOPK];
    __shared__ float s_iou[TOPK];
    __shared__ float s_ratio;
    __shared__ float s_lab[BS];

    const int b    = blockIdx.x;
    const int tid  = threadIdx.x;
    const int lane = tid & 31;
    const int wid  = tid >> 5;

    if (tid < BS) s_lab[tid] = (float)gt_labels[tid];

    const float gx1 = gt_bboxes[b * 4 + 0];
    const float gy1 = gt_bboxes[b * 4 + 1];
    const float gx2 = gt_bboxes[b * 4 + 2];
    const float gy2 = gt_bboxes[b * 4 + 3];
    const float area1 = fmaxf(gx2 - gx1, 0.f) * fmaxf(gy2 - gy1, 0.f);
    const int   label = gt_labels[b];

    const float* __restrict__ px1 = pd_bboxes + ((long)b * 4 + 0) * NA;
    const float* __restrict__ py1 = pd_bboxes + ((long)b * 4 + 1) * NA;
    const float* __restrict__ px2 = pd_bboxes + ((long)b * 4 + 2) * NA;
    const float* __restrict__ py2 = pd_bboxes + ((long)b * 4 + 3) * NA;
    const float* __restrict__ sc  = pd_scores + ((long)b * NC + label) * NA;
    float* __restrict__ mrow = mask_out + (long)b * NA;

    // ---- Phase A.1: align metric -> u32 candidates; zero mask row.
    unsigned sval[ELEM];
    #pragma unroll
    for (int i = 0; i < ELEM; i++) {
        int a = i * ATHR + tid;
        if (a < NA) {
            float bx1 = px1[a], by1 = py1[a], bx2 = px2[a], by2 = py2[a];
            float iw = fmaxf(fminf(gx2, bx2) - fmaxf(gx1, bx1), 0.f);
            float ih = fmaxf(fminf(gy2, by2) - fmaxf(gy1, by1), 0.f);
            float ov = iw * ih;
            float a2 = fmaxf(bx2 - bx1, 0.f) * fmaxf(by2 - by1, 0.f);
            float iou = ov / (area1 + a2 - ov + EPSF);
            float iou2 = iou * iou;
            float align = sc[a] * (iou2 * iou2 * iou2);
            sval[i] = __float_as_uint(align) + 1u;
            mrow[a] = 0.0f;
        } else {
            sval[i] = 0u;
        }
    }

    // ---- Stage 1: per-warp top-13 via REDUX (no shuffles, no barriers).
    #pragma unroll
    for (int k = 0; k < TOPK; k++) {
        // Thread-local best; ascending i scan keeps lowest anchor on ties.
        unsigned bv = 0u, ba = 0xFFFFFFFFu;
        #pragma unroll
        for (int i = 0; i < ELEM; i++) {
            unsigned a = (unsigned)(i * ATHR + tid);
            if (sval[i] > bv) { bv = sval[i]; ba = a; }
        }
        unsigned mv = __reduce_max_sync(0xFFFFFFFFu, bv);
        unsigned mi = __reduce_min_sync(0xFFFFFFFFu, (bv == mv) ? ba : 0xFFFFFFFFu);
        if (lane == 0) { s_candv[k * NWARP + wid] = mv; s_candi[k * NWARP + wid] = mi; }
        // Consume the exact winner (value AND index match).
        #pragma unroll
        for (int i = 0; i < ELEM; i++)
            if (sval[i] == mv && (unsigned)(i * ATHR + tid) == mi) sval[i] = 0u;
    }
    __syncthreads();

    // ---- Stage 2: warp 0 merges 32 sorted 13-lists (lex order preserved).
    if (wid == 0) {
        unsigned qv[TOPK], qi[TOPK];
        #pragma unroll
        for (int j = 0; j < TOPK; j++) {
            qv[j] = s_candv[j * NWARP + lane];
            qi[j] = s_candi[j * NWARP + lane];
        }
        #pragma unroll
        for (int k = 0; k < TOPK; k++) {
            // Within-lane list is (value desc, index asc): first max = lowest idx.
            unsigned bv = 0u, ba = 0xFFFFFFFFu;
            #pragma unroll
            for (int j = 0; j < TOPK; j++)
                if (qv[j] > bv) { bv = qv[j]; ba = qi[j]; }
            unsigned mv = __reduce_max_sync(0xFFFFFFFFu, bv);
            unsigned mi = __reduce_min_sync(0xFFFFFFFFu, (bv == mv) ? ba : 0xFFFFFFFFu);
            if (lane == 0) {
                s_topv[k] = __uint_as_float(mv - 1u);
                s_topi[k] = (int)mi;
            }
            #pragma unroll
            for (int j = 0; j < TOPK; j++)
                if (qv[j] == mv && qi[j] == mi) qv[j] = 0u;
        }
    }
    __syncthreads();

    // ---- Phase A.3: recompute raw IoU at winners (pos_overlaps).
    if (tid < TOPK) {
        int a = s_topi[tid];
        float bx1 = px1[a], by1 = py1[a], bx2 = px2[a], by2 = py2[a];
        float iw = fmaxf(fminf(gx2, bx2) - fmaxf(gx1, bx1), 0.f);
        float ih = fmaxf(fminf(gy2, by2) - fmaxf(gy1, by1), 0.f);
        float ov = iw * ih;
        float a2 = fmaxf(bx2 - bx1, 0.f) * fmaxf(by2 - by1, 0.f);
        s_iou[tid] = ov / (area1 + a2 - ov + EPSF);
    }
    __syncthreads();

    if (tid == 0) {
        float po = 0.f;
        #pragma unroll
        for (int k = 0; k < TOPK; k++) po = fmaxf(po, s_iou[k]);
        s_ratio = po / (s_topv[0] + EPSF);   // pos_overlaps / (pos_align + eps)
    }
    __syncthreads();

    if (s_topv[0] > EPSF && tid < TOPK) {
        int a = s_topi[tid];
        mrow[a] = 1.0f;
        float contrib = s_topv[tid] * s_ratio;
        atomicMax(&d_norm_bits[a], __float_as_uint(contrib));
    }
    // invalid row: mask all-zero (cnt>1 collapse), no norm contribution.

    // ---- Grid sync: single-wave ticket barrier (monotone, replay-safe).
    __syncthreads();
    if (tid == 0) {
        __threadfence();
        unsigned old = atomicAdd(&d_arrive, 1u);
        unsigned tgt = (old & ~(unsigned)(BS - 1)) + BS;
        while (*(volatile unsigned*)&d_arrive < tgt) { }
        __threadfence();
    }
    __syncthreads();

    // ---- Phase B: target_scores[a, j] = lab[j] * norm[a], (NA, BS) layout.
    const int a0 = b * PB_ANCH;
    const int nA = (a0 + PB_ANCH <= NA) ? PB_ANCH : (NA - a0);
    const int la = tid >> 4;            // 0..63 anchors per sweep
    const int j4 = (tid & 15) << 2;     // column group of 4

    #pragma unroll
    for (int it = 0; it < 3; it++) {    // 3*64 = 192 >= 132
        int al = it * 64 + la;
        if (al < nA) {
            int a = a0 + al;
            float nv = __uint_as_float(d_norm_bits[a]);
            float4 v = make_float4(nv * s_lab[j4 + 0], nv * s_lab[j4 + 1],
                                   nv * s_lab[j4 + 2], nv * s_lab[j4 + 3]);
            *reinterpret_cast<float4*>(target_out + (long)a * BS + j4) = v;
        }
    }
    __syncthreads();
    if (tid < nA) d_norm_bits[a0 + tid] = 0u;   // reset own slice for next call
}

extern "C" void kernel_launch(void* const* d_in, const int* in_sizes, int n_in,
                              void* d_out, int out_size) {
    const float* pd_scores = (const float*)d_in[0];
    const float* pd_bboxes = (const float*)d_in[1];
    const int*   gt_labels = (const int*)d_in[2];
    const float* gt_bboxes = (const float*)d_in[3];

    float* target = (float*)d_out;                       // (NA, BS)
    float* mask   = (float*)d_out + (size_t)NA * BS;     // (BS, NA)

    taa_fused<<<BS, ATHR>>>(pd_scores, pd_bboxes, gt_labels, gt_bboxes,
                            target, mask);
}

// round 10
// speedup vs baseline: 1.3607x; 1.1215x over previous
#include <cuda_runtime.h>

#define BS    64
#define NC    80
#define NA    8400
#define TOPK  13
#define EPSF  1e-9f

#define NTH   512
#define ELEM  17           // 512*17 = 8704 >= 8400
#define NWARP (NTH / 32)   // 16

#define PB_ANCH 132        // phase-B anchors per block: 64*132 = 8448 >= 8400

// norm_align_metric scratch (float bits). Zeroed at load; phase B resets its
// own slice after reading, so it's zeroed again before every next call.
__device__ unsigned int d_norm_bits[NA];
// Monotone ticket counter for the single-wave grid sync (never reset).
__device__ unsigned int d_arrive;

// Fused kernel: 64 blocks (one per batch row), 512 threads (128 regs/thread —
// room for full load batching + sval[17] without spills), single wave.
// Candidate encoding: sval = float_bits(align) + 1 (u32, monotone for align>=0;
// 0 = consumed/OOB sentinel). Winner per round = (max sval, min anchor index)
// == jax.lax.top_k tie order.
__global__ __launch_bounds__(NTH, 1) void taa_fused(
    const float* __restrict__ pd_scores,   // (BS, NC, NA)
    const float* __restrict__ pd_bboxes,   // (BS, 4, NA)
    const int*   __restrict__ gt_labels,   // (BS,)
    const float* __restrict__ gt_bboxes,   // (BS, 4)
    float*       __restrict__ target_out,  // (NA, BS)
    float*       __restrict__ mask_out)    // (BS, NA)
{
    __shared__ unsigned s_candv[TOPK * NWARP];
    __shared__ unsigned s_candi[TOPK * NWARP];
    __shared__ float s_topv[TOPK];
    __shared__ int   s_topi[TOPK];
    __shared__ float s_iou[TOPK];
    __shared__ float s_ratio;
    __shared__ float s_lab[BS];

    const int b    = blockIdx.x;
    const int tid  = threadIdx.x;
    const int lane = tid & 31;
    const int wid  = tid >> 5;

    if (tid < BS) s_lab[tid] = (float)gt_labels[tid];

    const float gx1 = gt_bboxes[b * 4 + 0];
    const float gy1 = gt_bboxes[b * 4 + 1];
    const float gx2 = gt_bboxes[b * 4 + 2];
    const float gy2 = gt_bboxes[b * 4 + 3];
    const float area1 = fmaxf(gx2 - gx1, 0.f) * fmaxf(gy2 - gy1, 0.f);
    const int   label = gt_labels[b];

    const float* __restrict__ px1 = pd_bboxes + ((long)b * 4 + 0) * NA;
    const float* __restrict__ py1 = pd_bboxes + ((long)b * 4 + 1) * NA;
    const float* __restrict__ px2 = pd_bboxes + ((long)b * 4 + 2) * NA;
    const float* __restrict__ py2 = pd_bboxes + ((long)b * 4 + 3) * NA;
    const float* __restrict__ sc  = pd_scores + ((long)b * NC + label) * NA;
    float* __restrict__ mrow = mask_out + (long)b * NA;

    // ---- Phase A.1: align metric -> u32 candidates; zero mask row.
    unsigned sval[ELEM];
    #pragma unroll
    for (int i = 0; i < ELEM; i++) {
        int a = i * NTH + tid;
        if (a < NA) {
            float bx1 = px1[a], by1 = py1[a], bx2 = px2[a], by2 = py2[a];
            float iw = fmaxf(fminf(gx2, bx2) - fmaxf(gx1, bx1), 0.f);
            float ih = fmaxf(fminf(gy2, by2) - fmaxf(gy1, by1), 0.f);
            float ov = iw * ih;
            float a2 = fmaxf(bx2 - bx1, 0.f) * fmaxf(by2 - by1, 0.f);
            float iou = __fdividef(ov, area1 + a2 - ov + EPSF);
            float iou2 = iou * iou;
            float align = sc[a] * (iou2 * iou2 * iou2);
            sval[i] = __float_as_uint(align) + 1u;
            mrow[a] = 0.0f;
        } else {
            sval[i] = 0u;
        }
    }

    // ---- Stage 1: per-warp top-13 via REDUX (no shuffles, no barriers).
    #pragma unroll
    for (int k = 0; k < TOPK; k++) {
        unsigned bv = 0u, ba = 0xFFFFFFFFu;
        #pragma unroll
        for (int i = 0; i < ELEM; i++) {
            unsigned a = (unsigned)(i * NTH + tid);
            if (sval[i] > bv) { bv = sval[i]; ba = a; }   // asc i: lowest anchor on tie
        }
        unsigned mv = __reduce_max_sync(0xFFFFFFFFu, bv);
        unsigned mi = __reduce_min_sync(0xFFFFFFFFu, (bv == mv) ? ba : 0xFFFFFFFFu);
        if (lane == 0) { s_candv[k * NWARP + wid] = mv; s_candi[k * NWARP + wid] = mi; }
        // Consume by index only (anchor index is unique).
        #pragma unroll
        for (int i = 0; i < ELEM; i++)
            if ((unsigned)(i * NTH + tid) == mi) sval[i] = 0u;
    }
    __syncthreads();

    // ---- Stage 2: warp 0 merges 16 sorted 13-lists (208 candidates).
    if (wid == 0) {
        unsigned qv[TOPK], qi[TOPK];
        #pragma unroll
        for (int j = 0; j < TOPK; j++) {
            qv[j] = (lane < NWARP) ? s_candv[j * NWARP + lane] : 0u;
            qi[j] = (lane < NWARP) ? s_candi[j * NWARP + lane] : 0xFFFFFFFFu;
        }
        #pragma unroll
        for (int k = 0; k < TOPK; k++) {
            unsigned bv = 0u, ba = 0xFFFFFFFFu;
            #pragma unroll
            for (int j = 0; j < TOPK; j++)
                if (qv[j] > bv) { bv = qv[j]; ba = qi[j]; }   // list is lex-sorted
            unsigned mv = __reduce_max_sync(0xFFFFFFFFu, bv);
            unsigned mi = __reduce_min_sync(0xFFFFFFFFu, (bv == mv) ? ba : 0xFFFFFFFFu);
            if (lane == 0) {
                s_topv[k] = __uint_as_float(mv - 1u);
                s_topi[k] = (int)mi;
            }
            #pragma unroll
            for (int j = 0; j < TOPK; j++)
                if (qi[j] == mi) qv[j] = 0u;   // anchors distinct across all lists
        }
    }
    __syncthreads();

    // ---- Phase A.3: recompute raw IoU at winners (pos_overlaps).
    if (tid < TOPK) {
        int a = s_topi[tid];
        float bx1 = px1[a], by1 = py1[a], bx2 = px2[a], by2 = py2[a];
        float iw = fmaxf(fminf(gx2, bx2) - fmaxf(gx1, bx1), 0.f);
        float ih = fmaxf(fminf(gy2, by2) - fmaxf(gy1, by1), 0.f);
        float ov = iw * ih;
        float a2 = fmaxf(bx2 - bx1, 0.f) * fmaxf(by2 - by1, 0.f);
        s_iou[tid] = __fdividef(ov, area1 + a2 - ov + EPSF);
    }
    __syncthreads();

    if (tid == 0) {
        float po = 0.f;
        #pragma unroll
        for (int k = 0; k < TOPK; k++) po = fmaxf(po, s_iou[k]);
        s_ratio = po / (s_topv[0] + EPSF);   // pos_overlaps / (pos_align + eps)
    }
    __syncthreads();

    if (s_topv[0] > EPSF && tid < TOPK) {
        int a = s_topi[tid];
        mrow[a] = 1.0f;
        float contrib = s_topv[tid] * s_ratio;
        atomicMax(&d_norm_bits[a], __float_as_uint(contrib));
    }
    // invalid row: mask all-zero (cnt>1 collapse), no norm contribution.

    // ---- Grid sync: single-wave ticket barrier (monotone, replay-safe).
    __syncthreads();
    if (tid == 0) {
        __threadfence();
        unsigned old = atomicAdd(&d_arrive, 1u);
        unsigned tgt = (old & ~(unsigned)(BS - 1)) + BS;
        while (*(volatile unsigned*)&d_arrive < tgt) { }
        __threadfence();
    }
    __syncthreads();

    // ---- Phase B: target_scores[a, j] = lab[j] * norm[a], (NA, BS) layout.
    const int a0 = b * PB_ANCH;
    const int nA = (a0 + PB_ANCH <= NA) ? PB_ANCH : (NA - a0);
    const int la = tid >> 4;            // 0..31 anchors per sweep
    const int j4 = (tid & 15) << 2;     // column group of 4

    #pragma unroll
    for (int it = 0; it < 5; it++) {    // 5*32 = 160 >= 132
        int al = it * 32 + la;
        if (al < nA) {
            int a = a0 + al;
            float nv = __uint_as_float(d_norm_bits[a]);
            float4 v = make_float4(nv * s_lab[j4 + 0], nv * s_lab[j4 + 1],
                                   nv * s_lab[j4 + 2], nv * s_lab[j4 + 3]);
            *reinterpret_cast<float4*>(target_out + (long)a * BS + j4) = v;
        }
    }
    __syncthreads();
    if (tid < nA) d_norm_bits[a0 + tid] = 0u;   // reset own slice for next call
}

extern "C" void kernel_launch(void* const* d_in, const int* in_sizes, int n_in,
                              void* d_out, int out_size) {
    const float* pd_scores = (const float*)d_in[0];
    const float* pd_bboxes = (const float*)d_in[1];
    const int*   gt_labels = (const int*)d_in[2];
    const float* gt_bboxes = (const float*)d_in[3];

    float* target = (float*)d_out;                       // (NA, BS)
    float* mask   = (float*)d_out + (size_t)NA * BS;     // (BS, NA)

    taa_fused<<<BS, NTH>>>(pd_scores, pd_bboxes, gt_labels, gt_bboxes,
                           target, mask);
}

// round 11
// speedup vs baseline: 1.3788x; 1.0133x over previous
#include <cuda_runtime.h>

#define BS    64
#define NC    80
#define NA    8400
#define TOPK  13
#define EPSF  1e-9f

#define NTH    512
#define NCHNK  (NA / 4)            // 2100 float4 chunks (exact)
#define ELEM4  5                   // ceil(2100 / 512)
#define NWARP  (NTH / 32)          // 16

#define PB_ANCH 132                // phase-B anchors per block: 64*132 >= 8400

// norm_align_metric scratch (float bits). Zeroed at load; phase B resets its
// own slice after reading, so it's zeroed again before every next call.
__device__ unsigned int d_norm_bits[NA];
// Monotone ticket counter for the single-wave grid sync (never reset).
__device__ unsigned int d_arrive;

// Fused kernel: 64 blocks (one per batch row), 512 threads, single wave.
// Loads are float4 (each thread owns 4 consecutive anchors per chunk).
// Candidate encoding: sval = float_bits(align) + 1 (u32, monotone for
// align>=0; 0 = consumed/OOB sentinel). Winner per round =
// (max sval, min anchor index) == jax.lax.top_k tie order.
__global__ __launch_bounds__(NTH, 1) void taa_fused(
    const float* __restrict__ pd_scores,   // (BS, NC, NA)
    const float* __restrict__ pd_bboxes,   // (BS, 4, NA)
    const int*   __restrict__ gt_labels,   // (BS,)
    const float* __restrict__ gt_bboxes,   // (BS, 4)
    float*       __restrict__ target_out,  // (NA, BS)
    float*       __restrict__ mask_out)    // (BS, NA)
{
    __shared__ unsigned s_candv[TOPK * NWARP];
    __shared__ unsigned s_candi[TOPK * NWARP];
    __shared__ float s_topv[TOPK];
    __shared__ int   s_topi[TOPK];
    __shared__ float s_iou[TOPK];
    __shared__ float s_ratio;
    __shared__ float s_lab[BS];

    const int b    = blockIdx.x;
    const int tid  = threadIdx.x;
    const int lane = tid & 31;
    const int wid  = tid >> 5;

    if (tid < BS) s_lab[tid] = (float)gt_labels[tid];

    const float gx1 = gt_bboxes[b * 4 + 0];
    const float gy1 = gt_bboxes[b * 4 + 1];
    const float gx2 = gt_bboxes[b * 4 + 2];
    const float gy2 = gt_bboxes[b * 4 + 3];
    const float area1 = fmaxf(gx2 - gx1, 0.f) * fmaxf(gy2 - gy1, 0.f);
    const int   label = gt_labels[b];

    const float4* __restrict__ px1 = (const float4*)(pd_bboxes + ((long)b * 4 + 0) * NA);
    const float4* __restrict__ py1 = (const float4*)(pd_bboxes + ((long)b * 4 + 1) * NA);
    const float4* __restrict__ px2 = (const float4*)(pd_bboxes + ((long)b * 4 + 2) * NA);
    const float4* __restrict__ py2 = (const float4*)(pd_bboxes + ((long)b * 4 + 3) * NA);
    const float4* __restrict__ sc  = (const float4*)(pd_scores + ((long)b * NC + label) * NA);
    float* __restrict__ mrow = mask_out + (long)b * NA;
    float4* __restrict__ mrow4 = (float4*)mrow;

    // ---- Phase A.1: align metric -> u32 candidates (float4 loads).
    unsigned sval[ELEM4 * 4];
    #pragma unroll
    for (int i = 0; i < ELEM4; i++) {
        int c = i * NTH + tid;                 // chunk of 4 consecutive anchors
        if (c < NCHNK) {
            float4 vx1 = px1[c], vy1 = py1[c], vx2 = px2[c], vy2 = py2[c];
            float4 vsc = sc[c];
            #pragma unroll
            for (int j = 0; j < 4; j++) {
                float bx1 = (&vx1.x)[j], by1 = (&vy1.x)[j];
                float bx2 = (&vx2.x)[j], by2 = (&vy2.x)[j];
                float iw = fmaxf(fminf(gx2, bx2) - fmaxf(gx1, bx1), 0.f);
                float ih = fmaxf(fminf(gy2, by2) - fmaxf(gy1, by1), 0.f);
                float ov = iw * ih;
                float a2 = fmaxf(bx2 - bx1, 0.f) * fmaxf(by2 - by1, 0.f);
                float iou = __fdividef(ov, area1 + a2 - ov + EPSF);
                float iou2 = iou * iou;
                float align = (&vsc.x)[j] * (iou2 * iou2 * iou2);
                sval[i * 4 + j] = __float_as_uint(align) + 1u;
            }
            mrow4[c] = make_float4(0.f, 0.f, 0.f, 0.f);
        } else {
            #pragma unroll
            for (int j = 0; j < 4; j++) sval[i * 4 + j] = 0u;
        }
    }

    // ---- Stage 1: per-warp top-13 via REDUX.
    #pragma unroll
    for (int k = 0; k < TOPK; k++) {
        // Local scan: (i,j) ascending == anchor ascending for fixed tid,
        // so strict '>' keeps the lowest anchor on value ties.
        unsigned bv = 0u, ba = 0xFFFFFFFFu;
        #pragma unroll
        for (int i = 0; i < ELEM4; i++) {
            #pragma unroll
            for (int j = 0; j < 4; j++) {
                unsigned a = (unsigned)(((i * NTH + tid) << 2) + j);
                if (sval[i * 4 + j] > bv) { bv = sval[i * 4 + j]; ba = a; }
            }
        }
        unsigned mv = __reduce_max_sync(0xFFFFFFFFu, bv);
        unsigned mi = __reduce_min_sync(0xFFFFFFFFu, (bv == mv) ? ba : 0xFFFFFFFFu);
        if (lane == 0) { s_candv[k * NWARP + wid] = mv; s_candi[k * NWARP + wid] = mi; }
        // Consume by unique anchor index (static sval indices -> predicated).
        #pragma unroll
        for (int i = 0; i < ELEM4; i++) {
            #pragma unroll
            for (int j = 0; j < 4; j++)
                if ((unsigned)(((i * NTH + tid) << 2) + j) == mi) sval[i * 4 + j] = 0u;
        }
    }
    __syncthreads();

    // ---- Stage 2: warp 0 merges 16 sorted 13-lists (208 candidates).
    if (wid == 0) {
        unsigned qv[TOPK], qi[TOPK];
        #pragma unroll
        for (int j = 0; j < TOPK; j++) {
            qv[j] = (lane < NWARP) ? s_candv[j * NWARP + lane] : 0u;
            qi[j] = (lane < NWARP) ? s_candi[j * NWARP + lane] : 0xFFFFFFFFu;
        }
        #pragma unroll
        for (int k = 0; k < TOPK; k++) {
            unsigned bv = 0u, ba = 0xFFFFFFFFu;
            #pragma unroll
            for (int j = 0; j < TOPK; j++)
                if (qv[j] > bv) { bv = qv[j]; ba = qi[j]; }   // lane list lex-sorted
            unsigned mv = __reduce_max_sync(0xFFFFFFFFu, bv);
            unsigned mi = __reduce_min_sync(0xFFFFFFFFu, (bv == mv) ? ba : 0xFFFFFFFFu);
            if (lane == 0) {
                s_topv[k] = __uint_as_float(mv - 1u);
                s_topi[k] = (int)mi;
            }
            #pragma unroll
            for (int j = 0; j < TOPK; j++)
                if (qi[j] == mi) qv[j] = 0u;   // anchors distinct across lists
        }
    }
    __syncthreads();

    // ---- Phase A.3: recompute raw IoU at winners (pos_overlaps).
    if (tid < TOPK) {
        int a = s_topi[tid];
        const float* pb = pd_bboxes + (long)b * 4 * NA;
        float bx1 = pb[a], by1 = pb[NA + a], bx2 = pb[2 * NA + a], by2 = pb[3 * NA + a];
        float iw = fmaxf(fminf(gx2, bx2) - fmaxf(gx1, bx1), 0.f);
        float ih = fmaxf(fminf(gy2, by2) - fmaxf(gy1, by1), 0.f);
        float ov = iw * ih;
        float a2 = fmaxf(bx2 - bx1, 0.f) * fmaxf(by2 - by1, 0.f);
        s_iou[tid] = __fdividef(ov, area1 + a2 - ov + EPSF);
    }
    __syncthreads();

    if (tid == 0) {
        float po = 0.f;
        #pragma unroll
        for (int k = 0; k < TOPK; k++) po = fmaxf(po, s_iou[k]);
        s_ratio = po / (s_topv[0] + EPSF);   // pos_overlaps / (pos_align + eps)
    }
    __syncthreads();

    if (s_topv[0] > EPSF && tid < TOPK) {
        int a = s_topi[tid];
        mrow[a] = 1.0f;
        float contrib = s_topv[tid] * s_ratio;
        atomicMax(&d_norm_bits[a], __float_as_uint(contrib));
    }
    // invalid row: mask all-zero (cnt>1 collapse), no norm contribution.

    // ---- Grid sync: single-wave ticket barrier (monotone, replay-safe).
    __syncthreads();
    if (tid == 0) {
        __threadfence();
        unsigned old = atomicAdd(&d_arrive, 1u);
        unsigned tgt = (old & ~(unsigned)(BS - 1)) + BS;
        while (*(volatile unsigned*)&d_arrive < tgt) { }
        __threadfence();
    }
    __syncthreads();

    // ---- Phase B: target_scores[a, j] = lab[j] * norm[a], (NA, BS) layout.
    const int a0 = b * PB_ANCH;
    const int nA = (a0 + PB_ANCH <= NA) ? PB_ANCH : (NA - a0);
    const int la = tid >> 4;            // 0..31 anchors per sweep
    const int j4 = (tid & 15) << 2;     // column group of 4

    #pragma unroll
    for (int it = 0; it < 5; it++) {    // 5*32 = 160 >= 132
        int al = it * 32 + la;
        if (al < nA) {
            int a = a0 + al;
            float nv = __uint_as_float(d_norm_bits[a]);
            float4 v = make_float4(nv * s_lab[j4 + 0], nv * s_lab[j4 + 1],
                                   nv * s_lab[j4 + 2], nv * s_lab[j4 + 3]);
            *reinterpret_cast<float4*>(target_out + (long)a * BS + j4) = v;
        }
    }
    __syncthreads();
    if (tid < nA) d_norm_bits[a0 + tid] = 0u;   // reset own slice for next call
}

extern "C" void kernel_launch(void* const* d_in, const int* in_sizes, int n_in,
                              void* d_out, int out_size) {
    const float* pd_scores = (const float*)d_in[0];
    const float* pd_bboxes = (const float*)d_in[1];
    const int*   gt_labels = (const int*)d_in[2];
    const float* gt_bboxes = (const float*)d_in[3];

    float* target = (float*)d_out;                       // (NA, BS)
    float* mask   = (float*)d_out + (size_t)NA * BS;     // (BS, NA)

    taa_fused<<<BS, NTH>>>(pd_scores, pd_bboxes, gt_labels, gt_bboxes,
                           target, mask);
}

// round 12
// speedup vs baseline: 1.4191x; 1.0292x over previous
#include <cuda_runtime.h>

#define BS    64
#define NC    80
#define NA    8400
#define TOPK  13
#define EPSF  1e-9f

#define NTH    512
#define NCHNK  (NA / 4)            // 2100 float4 chunks (exact)
#define ELEM4  5                   // ceil(2100 / 512)
#define NWARP  (NTH / 32)          // 16
#define CAP    256                 // survivor buffer capacity

#define PB_ANCH 132                // phase-B anchors per block: 64*132 >= 8400

// norm_align_metric scratch (float bits). Zeroed at load; phase B resets its
// own slice after reading, so it's zeroed again before every next call.
__device__ unsigned int d_norm_bits[NA];
// Monotone ticket counter for the single-wave grid sync (never reset).
__device__ unsigned int d_arrive;

// Fused kernel: 64 blocks (one per batch row), 512 threads, single wave.
// Candidate encoding: sval = float_bits(align) + 1 (u32, monotone for
// align>=0; 0 = consumed/OOB sentinel). top_k tie order = (max val, min anchor).
//
// Top-13 strategy: threshold prefilter. L = 13th largest of the 16 warp
// maxima is a valid lower bound on the block's 13th-largest value (the block
// contains those 16 values), so filtering sval >= L keeps a superset of the
// exact top-13 (including all ties). Survivors are compacted to smem and
// warp 0 selects the exact top-13. If survivors overflow CAP (pathological
// tie storm), fall back to the exact 13-round per-warp REDUX path.
__global__ __launch_bounds__(NTH, 1) void taa_fused(
    const float* __restrict__ pd_scores,   // (BS, NC, NA)
    const float* __restrict__ pd_bboxes,   // (BS, 4, NA)
    const int*   __restrict__ gt_labels,   // (BS,)
    const float* __restrict__ gt_bboxes,   // (BS, 4)
    float*       __restrict__ target_out,  // (NA, BS)
    float*       __restrict__ mask_out)    // (BS, NA)
{
    __shared__ unsigned s_wmax[NWARP];
    __shared__ unsigned s_cnt;
    __shared__ unsigned s_L;
    __shared__ unsigned s_bufv[CAP];
    __shared__ unsigned s_bufi[CAP];
    __shared__ unsigned s_candv[TOPK * NWARP];   // fallback only
    __shared__ unsigned s_candi[TOPK * NWARP];   // fallback only
    __shared__ float s_topv[TOPK];
    __shared__ int   s_topi[TOPK];
    __shared__ float s_iou[TOPK];
    __shared__ float s_ratio;
    __shared__ float s_lab[BS];

    const int b    = blockIdx.x;
    const int tid  = threadIdx.x;
    const int lane = tid & 31;
    const int wid  = tid >> 5;

    if (tid < BS) s_lab[tid] = (float)gt_labels[tid];
    if (tid == 0) s_cnt = 0u;

    const float gx1 = gt_bboxes[b * 4 + 0];
    const float gy1 = gt_bboxes[b * 4 + 1];
    const float gx2 = gt_bboxes[b * 4 + 2];
    const float gy2 = gt_bboxes[b * 4 + 3];
    const float area1 = fmaxf(gx2 - gx1, 0.f) * fmaxf(gy2 - gy1, 0.f);
    const int   label = gt_labels[b];

    const float4* __restrict__ px1 = (const float4*)(pd_bboxes + ((long)b * 4 + 0) * NA);
    const float4* __restrict__ py1 = (const float4*)(pd_bboxes + ((long)b * 4 + 1) * NA);
    const float4* __restrict__ px2 = (const float4*)(pd_bboxes + ((long)b * 4 + 2) * NA);
    const float4* __restrict__ py2 = (const float4*)(pd_bboxes + ((long)b * 4 + 3) * NA);
    const float4* __restrict__ sc  = (const float4*)(pd_scores + ((long)b * NC + label) * NA);
    float* __restrict__ mrow = mask_out + (long)b * NA;
    float4* __restrict__ mrow4 = (float4*)mrow;

    // ---- Phase A.1: align metric -> u32 candidates (float4 loads).
    unsigned sval[ELEM4 * 4];
    #pragma unroll
    for (int i = 0; i < ELEM4; i++) {
        int c = i * NTH + tid;
        if (c < NCHNK) {
            float4 vx1 = px1[c], vy1 = py1[c], vx2 = px2[c], vy2 = py2[c];
            float4 vsc = sc[c];
            #pragma unroll
            for (int j = 0; j < 4; j++) {
                float bx1 = (&vx1.x)[j], by1 = (&vy1.x)[j];
                float bx2 = (&vx2.x)[j], by2 = (&vy2.x)[j];
                float iw = fmaxf(fminf(gx2, bx2) - fmaxf(gx1, bx1), 0.f);
                float ih = fmaxf(fminf(gy2, by2) - fmaxf(gy1, by1), 0.f);
                float ov = iw * ih;
                float a2 = fmaxf(bx2 - bx1, 0.f) * fmaxf(by2 - by1, 0.f);
                float iou = __fdividef(ov, area1 + a2 - ov + EPSF);
                float iou2 = iou * iou;
                float align = (&vsc.x)[j] * (iou2 * iou2 * iou2);
                sval[i * 4 + j] = __float_as_uint(align) + 1u;
            }
            mrow4[c] = make_float4(0.f, 0.f, 0.f, 0.f);
        } else {
            #pragma unroll
            for (int j = 0; j < 4; j++) sval[i * 4 + j] = 0u;
        }
    }

    // ---- Per-thread local max -> per-warp max.
    unsigned bv = 0u;
    #pragma unroll
    for (int e = 0; e < ELEM4 * 4; e++) bv = (sval[e] > bv) ? sval[e] : bv;
    unsigned wmv = __reduce_max_sync(0xFFFFFFFFu, bv);
    if (lane == 0) s_wmax[wid] = wmv;
    __syncthreads();

    // ---- Warp 0: L = 13th largest (with multiplicity) of the 16 warp maxima.
    if (wid == 0) {
        unsigned v = (lane < NWARP) ? s_wmax[lane] : 0u;
        unsigned Lv = 0u;
        #pragma unroll
        for (int k = 0; k < TOPK; k++) {
            unsigned mv = __reduce_max_sync(0xFFFFFFFFu, v);
            unsigned ml = __reduce_min_sync(0xFFFFFFFFu,
                                            (v == mv) ? (unsigned)lane : 0xFFFFFFFFu);
            if ((unsigned)lane == ml) v = 0u;
            Lv = mv;
        }
        if (lane == 0) s_L = Lv;
    }
    __syncthreads();

    // ---- Filter & compact survivors (sval >= L). OOB sval=0 < L (L >= 1).
    {
        const unsigned L = s_L;
        #pragma unroll
        for (int i = 0; i < ELEM4; i++) {
            #pragma unroll
            for (int j = 0; j < 4; j++) {
                if (sval[i * 4 + j] >= L) {
                    unsigned pos = atomicAdd(&s_cnt, 1u);
                    if (pos < CAP) {
                        s_bufv[pos] = sval[i * 4 + j];
                        s_bufi[pos] = (unsigned)(((i * NTH + tid) << 2) + j);
                    }
                }
            }
        }
    }
    __syncthreads();

    const unsigned ncand = s_cnt;
    if (ncand <= CAP) {
        // ---- Fast path: warp 0 selects exact top-13 of the survivors.
        if (wid == 0) {
            const int nper = (int)((ncand + 31u) >> 5);
            for (int k = 0; k < TOPK; k++) {
                unsigned bv2 = 0u, ba2 = 0xFFFFFFFFu;
                int bslot = 0;
                for (int j = 0; j < nper; j++) {
                    int p = lane + (j << 5);
                    if (p < (int)ncand) {
                        unsigned v = s_bufv[p], a = s_bufi[p];
                        if (v > bv2 || (v == bv2 && a < ba2)) { bv2 = v; ba2 = a; bslot = p; }
                    }
                }
                unsigned mv = __reduce_max_sync(0xFFFFFFFFu, bv2);
                unsigned mi = __reduce_min_sync(0xFFFFFFFFu,
                                                (bv2 == mv) ? ba2 : 0xFFFFFFFFu);
                if (lane == 0) {
                    s_topv[k] = __uint_as_float(mv - 1u);
                    s_topi[k] = (int)mi;
                }
                if (bv2 == mv && ba2 == mi) s_bufv[bslot] = 0u;  // consume (owner lane)
            }
        }
    } else {
        // ---- Fallback (exact, tie-storm safe): per-warp 13 rounds + merge.
        #pragma unroll
        for (int k = 0; k < TOPK; k++) {
            unsigned fv = 0u, fa = 0xFFFFFFFFu;
            #pragma unroll
            for (int i = 0; i < ELEM4; i++) {
                #pragma unroll
                for (int j = 0; j < 4; j++) {
                    unsigned a = (unsigned)(((i * NTH + tid) << 2) + j);
                    if (sval[i * 4 + j] > fv) { fv = sval[i * 4 + j]; fa = a; }
                }
            }
            unsigned mv = __reduce_max_sync(0xFFFFFFFFu, fv);
            unsigned mi = __reduce_min_sync(0xFFFFFFFFu, (fv == mv) ? fa : 0xFFFFFFFFu);
            if (lane == 0) { s_candv[k * NWARP + wid] = mv; s_candi[k * NWARP + wid] = mi; }
            #pragma unroll
            for (int i = 0; i < ELEM4; i++) {
                #pragma unroll
                for (int j = 0; j < 4; j++)
                    if ((unsigned)(((i * NTH + tid) << 2) + j) == mi) sval[i * 4 + j] = 0u;
            }
        }
        __syncthreads();
        if (wid == 0) {
            unsigned qv[TOPK], qi[TOPK];
            #pragma unroll
            for (int j = 0; j < TOPK; j++) {
                qv[j] = (lane < NWARP) ? s_candv[j * NWARP + lane] : 0u;
                qi[j] = (lane < NWARP) ? s_candi[j * NWARP + lane] : 0xFFFFFFFFu;
            }
            #pragma unroll
            for (int k = 0; k < TOPK; k++) {
                unsigned fv = 0u, fa = 0xFFFFFFFFu;
                #pragma unroll
                for (int j = 0; j < TOPK; j++)
                    if (qv[j] > fv) { fv = qv[j]; fa = qi[j]; }
                unsigned mv = __reduce_max_sync(0xFFFFFFFFu, fv);
                unsigned mi = __reduce_min_sync(0xFFFFFFFFu, (fv == mv) ? fa : 0xFFFFFFFFu);
                if (lane == 0) {
                    s_topv[k] = __uint_as_float(mv - 1u);
                    s_topi[k] = (int)mi;
                }
                #pragma unroll
                for (int j = 0; j < TOPK; j++)
                    if (qi[j] == mi) qv[j] = 0u;
            }
        }
    }
    __syncthreads();

    // ---- Phase A.3: recompute raw IoU at winners (pos_overlaps).
    if (tid < TOPK) {
        int a = s_topi[tid];
        const float* pb = pd_bboxes + (long)b * 4 * NA;
        float bx1 = pb[a], by1 = pb[NA + a], bx2 = pb[2 * NA + a], by2 = pb[3 * NA + a];
        float iw = fmaxf(fminf(gx2, bx2) - fmaxf(gx1, bx1), 0.f);
        float ih = fmaxf(fminf(gy2, by2) - fmaxf(gy1, by1), 0.f);
        float ov = iw * ih;
        float a2 = fmaxf(bx2 - bx1, 0.f) * fmaxf(by2 - by1, 0.f);
        s_iou[tid] = __fdividef(ov, area1 + a2 - ov + EPSF);
    }
    __syncthreads();

    if (tid == 0) {
        float po = 0.f;
        #pragma unroll
        for (int k = 0; k < TOPK; k++) po = fmaxf(po, s_iou[k]);
        s_ratio = po / (s_topv[0] + EPSF);   // pos_overlaps / (pos_align + eps)
    }
    __syncthreads();

    if (s_topv[0] > EPSF && tid < TOPK) {
        int a = s_topi[tid];
        mrow[a] = 1.0f;
        float contrib = s_topv[tid] * s_ratio;
        atomicMax(&d_norm_bits[a], __float_as_uint(contrib));
    }
    // invalid row: mask all-zero (cnt>1 collapse), no norm contribution.

    // ---- Grid sync: single-wave ticket barrier (monotone, replay-safe).
    __syncthreads();
    if (tid == 0) {
        __threadfence();
        unsigned old = atomicAdd(&d_arrive, 1u);
        unsigned tgt = (old & ~(unsigned)(BS - 1)) + BS;
        while (*(volatile unsigned*)&d_arrive < tgt) { }
        __threadfence();
    }
    __syncthreads();

    // ---- Phase B: target_scores[a, j] = lab[j] * norm[a], (NA, BS) layout.
    const int a0 = b * PB_ANCH;
    const int nA = (a0 + PB_ANCH <= NA) ? PB_ANCH : (NA - a0);
    const int la = tid >> 4;            // 0..31 anchors per sweep
    const int j4 = (tid & 15) << 2;     // column group of 4

    #pragma unroll
    for (int it = 0; it < 5; it++) {    // 5*32 = 160 >= 132
        int al = it * 32 + la;
        if (al < nA) {
            int a = a0 + al;
            float nv = __uint_as_float(d_norm_bits[a]);
            float4 v = make_float4(nv * s_lab[j4 + 0], nv * s_lab[j4 + 1],
                                   nv * s_lab[j4 + 2], nv * s_lab[j4 + 3]);
            *reinterpret_cast<float4*>(target_out + (long)a * BS + j4) = v;
        }
    }
    __syncthreads();
    if (tid < nA) d_norm_bits[a0 + tid] = 0u;   // reset own slice for next call
}

extern "C" void kernel_launch(void* const* d_in, const int* in_sizes, int n_in,
                              void* d_out, int out_size) {
    const float* pd_scores = (const float*)d_in[0];
    const float* pd_bboxes = (const float*)d_in[1];
    const int*   gt_labels = (const int*)d_in[2];
    const float* gt_bboxes = (const float*)d_in[3];

    float* target = (float*)d_out;                       // (NA, BS)
    float* mask   = (float*)d_out + (size_t)NA * BS;     // (BS, NA)

    taa_fused<<<BS, NTH>>>(pd_scores, pd_bboxes, gt_labels, gt_bboxes,
                           target, mask);
}